// round 8
// baseline (speedup 1.0000x reference)
#include <cuda_runtime.h>

#define HU      64
#define G4      256
#define T_STEPS 256
#define BATCH   4096
#define BB      32          // batch rows per K2 block
#define K2_NTH  512
#define K1_BT   128         // batch rows per K1 tile
#define K1_NTH  256
#define K1_GRID 512
#define K1_ITER 16          // tiles per K1 block (512*16 = 8192 = 256 t * 32 btiles)

typedef unsigned long long u64;

// 1 GB scratch: xz = x@W1 + b1, layout [t][j][b]
__device__ float XZ[(size_t)T_STEPS * G4 * BATCH];

__device__ __forceinline__ u64 fma2(u64 a, u64 b, u64 c) {
    u64 d;
    asm("fma.rn.f32x2 %0, %1, %2, %3;" : "=l"(d) : "l"(a), "l"(b), "l"(c));
    return d;
}
__device__ __forceinline__ float hadd2(u64 v) {
    float l, h;
    asm("mov.b64 {%0, %1}, %2;" : "=f"(l), "=f"(h) : "l"(v));
    return l + h;
}
__device__ __forceinline__ float fexp(float x) {
    float y;
    asm("ex2.approx.f32 %0, %1;" : "=f"(y) : "f"(x * 1.4426950408889634f));
    return y;
}
__device__ __forceinline__ float frcp(float x) {
    float y;
    asm("rcp.approx.f32 %0, %1;" : "=f"(y) : "f"(x));
    return y;
}
__device__ __forceinline__ float sigf(float x) { return frcp(1.0f + fexp(-x)); }
__device__ __forceinline__ float tanhfast(float x) {
    return fmaf(2.0f, frcp(1.0f + fexp(-2.0f * x)), -1.0f);
}

// ===================== K1: xz prepass, writes [t][j][b] =====================
// 512 blocks; each loads W1 ONCE, then loops over 16 (t, b-tile) tiles.
__global__ void __launch_bounds__(K1_NTH)
k1_xz(const float* __restrict__ x, const float* __restrict__ W1,
      const float* __restrict__ b1)
{
    extern __shared__ __align__(16) float sm1[];
    float* W1p = sm1;               // 8192 floats (k4-packed transpose)
    float* xs  = sm1 + 8192;        // 128 rows * 32 f

    const int tid = threadIdx.x;

    for (int i = tid; i < 32 * G4; i += K1_NTH) {
        int f = i >> 8, j = i & 255;
        W1p[((f >> 2) << 10) + (j << 2) + (f & 3)] = W1[i];
    }

    const int u  = tid & 63;
    const int bg = tid >> 6;
    float bj[4];
#pragma unroll
    for (int jj = 0; jj < 4; jj++) bj[jj] = b1[u + 64 * jj];

    for (int it = 0; it < K1_ITER; it++) {
        const int tile = it * K1_GRID + blockIdx.x;
        const int t  = tile >> 5;
        const int b0 = (tile & 31) * K1_BT;

        __syncthreads();   // protect xs reuse (and W1p on first iter)
        for (int i = tid; i < K1_BT * 8; i += K1_NTH) {   // 1024 float4
            int row = i >> 3, f4 = i & 7;
            ((float4*)xs)[row * 8 + f4] =
                *(const float4*)(x + ((size_t)(b0 + row) * T_STEPS + t) * 32 + f4 * 4);
        }
        __syncthreads();

        for (int rep = 0; rep < 4; rep++) {
            const int rb = bg * 32 + rep * 8;
            u64 acc[4][8];
#pragma unroll
            for (int jj = 0; jj < 4; jj++)
#pragma unroll
                for (int b = 0; b < 8; b++) acc[jj][b] = 0ULL;

#pragma unroll
            for (int f4 = 0; f4 < 8; f4++) {
                u64 w[4][2];
#pragma unroll
                for (int jj = 0; jj < 4; jj++) {
                    ulonglong2 W = *(const ulonglong2*)&W1p[(f4 << 10) + ((u + 64 * jj) << 2)];
                    w[jj][0] = W.x; w[jj][1] = W.y;
                }
#pragma unroll
                for (int b = 0; b < 8; b++) {
                    ulonglong2 X = *(const ulonglong2*)&xs[(rb + b) * 32 + (f4 << 2)];
#pragma unroll
                    for (int jj = 0; jj < 4; jj++) {
                        acc[jj][b] = fma2(X.x, w[jj][0], acc[jj][b]);
                        acc[jj][b] = fma2(X.y, w[jj][1], acc[jj][b]);
                    }
                }
            }
#pragma unroll
            for (int jj = 0; jj < 4; jj++) {
                float z[8];
#pragma unroll
                for (int b = 0; b < 8; b++) z[b] = hadd2(acc[jj][b]) + bj[jj];
                float4* dst = (float4*)&XZ[((size_t)t * G4 + u + 64 * jj) * BATCH + b0 + rb];
                dst[0] = make_float4(z[0], z[1], z[2], z[3]);
                dst[1] = make_float4(z[4], z[5], z[6], z[7]);
            }
        }
    }
}

// ===================== K2: fused 2-layer recurrence + dense heads =====================
// 512 threads: u = tid&63 (unit, all 4 gates), bg = tid>>6 (0..7), rows = bg*4 .. +3.
// smem (floats): U1p @0, W2p @16384, U2p @32768; h1 @49152 [2][32][64], h2 @53248.
#define K2_SMF 57344

__global__ void __launch_bounds__(K2_NTH, 1)
k2_main(const float* __restrict__ U1, const float* __restrict__ W2,
        const float* __restrict__ U2, const float* __restrict__ b2,
        const float* __restrict__ Wd, const float* __restrict__ bd,
        const float* __restrict__ Wo, const float* __restrict__ bo,
        float* __restrict__ out)
{
    extern __shared__ __align__(16) float sm[];
    float* U1p = sm;
    float* W2p = sm + 16384;
    float* U2p = sm + 32768;
    float* h1s = sm + 49152;
    float* h2s = sm + 53248;

    const int tid = threadIdx.x;

    for (int i = tid; i < HU * G4; i += K2_NTH) {
        int k = i >> 8, j = i & 255;
        int d = ((k >> 2) << 10) + (j << 2) + (k & 3);
        float a = U1[i], b = W2[i], c = U2[i];
        U1p[d] = a; W2p[d] = b; U2p[d] = c;
    }
    for (int i = tid; i < 4096; i += K2_NTH) { h1s[i] = 0.0f; h2s[i] = 0.0f; }

    const int u   = tid & 63;
    const int bg  = tid >> 6;
    const int b0g = bg * 4;
    const int bglob = blockIdx.x * BB;

    float b2j[4];
#pragma unroll
    for (int jj = 0; jj < 4; jj++) b2j[jj] = b2[u + 64 * jj];

    float c1[4], c2[4];
#pragma unroll
    for (int b = 0; b < 4; b++) { c1[b] = 0.0f; c2[b] = 0.0f; }

    // preload xz for t=0 (one float4 per gate column = 4 batch rows)
    float4 xz[4];
#pragma unroll
    for (int jj = 0; jj < 4; jj++)
        xz[jj] = *(const float4*)&XZ[((size_t)(u + 64 * jj)) * BATCH + bglob + b0g];

    __syncthreads();

    int cur = 0;
    for (int t = 0; t < T_STEPS; t++) {
        const int nxt = cur ^ 1;

        // ---------- phase 1: z1 = xz + h1(t-1) @ U1 ; update c1, h1 ----------
        {
            u64 acc[4][4];
#pragma unroll
            for (int jj = 0; jj < 4; jj++)
#pragma unroll
                for (int b = 0; b < 4; b++) acc[jj][b] = 0ULL;

#pragma unroll 4
            for (int k4 = 0; k4 < 16; k4++) {
                u64 w[4][2];
#pragma unroll
                for (int jj = 0; jj < 4; jj++) {
                    ulonglong2 W = *(const ulonglong2*)&U1p[(k4 << 10) + ((u + 64 * jj) << 2)];
                    w[jj][0] = W.x; w[jj][1] = W.y;
                }
#pragma unroll
                for (int b = 0; b < 4; b++) {
                    ulonglong2 H = *(const ulonglong2*)&h1s[((cur << 5) + b0g + b) * 64 + (k4 << 2)];
#pragma unroll
                    for (int jj = 0; jj < 4; jj++) {
                        acc[jj][b] = fma2(H.x, w[jj][0], acc[jj][b]);
                        acc[jj][b] = fma2(H.y, w[jj][1], acc[jj][b]);
                    }
                }
            }

            float z[4][4];
#pragma unroll
            for (int jj = 0; jj < 4; jj++) {
                z[jj][0] = hadd2(acc[jj][0]) + xz[jj].x;
                z[jj][1] = hadd2(acc[jj][1]) + xz[jj].y;
                z[jj][2] = hadd2(acc[jj][2]) + xz[jj].z;
                z[jj][3] = hadd2(acc[jj][3]) + xz[jj].w;
            }
#pragma unroll
            for (int b = 0; b < 4; b++) {
                c1[b] = sigf(z[1][b]) * c1[b] + sigf(z[0][b]) * tanhfast(z[2][b]);
                h1s[((nxt << 5) + b0g + b) * 64 + u] = sigf(z[3][b]) * tanhfast(c1[b]);
            }
        }
        __syncthreads();

        // ---------- phase 2: z2 = h1(t)@W2 + h2(t-1)@U2 + b2 ; update c2, h2 ----------
        {
            // prefetch next step's xz early (consumed after the next barrier)
            const int tn = (t + 1) & 255;
#pragma unroll
            for (int jj = 0; jj < 4; jj++)
                xz[jj] = *(const float4*)
                    &XZ[((size_t)tn * G4 + u + 64 * jj) * BATCH + bglob + b0g];

            u64 acc[4][4];
#pragma unroll
            for (int jj = 0; jj < 4; jj++)
#pragma unroll
                for (int b = 0; b < 4; b++) acc[jj][b] = 0ULL;

#pragma unroll 2
            for (int k4 = 0; k4 < 16; k4++) {
                u64 w2[4][2], v2[4][2];
#pragma unroll
                for (int jj = 0; jj < 4; jj++) {
                    ulonglong2 W = *(const ulonglong2*)&W2p[(k4 << 10) + ((u + 64 * jj) << 2)];
                    w2[jj][0] = W.x; w2[jj][1] = W.y;
                    ulonglong2 V = *(const ulonglong2*)&U2p[(k4 << 10) + ((u + 64 * jj) << 2)];
                    v2[jj][0] = V.x; v2[jj][1] = V.y;
                }
#pragma unroll
                for (int b = 0; b < 4; b++) {
                    ulonglong2 Hn = *(const ulonglong2*)&h1s[((nxt << 5) + b0g + b) * 64 + (k4 << 2)];
                    ulonglong2 Ho = *(const ulonglong2*)&h2s[((cur << 5) + b0g + b) * 64 + (k4 << 2)];
#pragma unroll
                    for (int jj = 0; jj < 4; jj++) {
                        acc[jj][b] = fma2(Hn.x, w2[jj][0], acc[jj][b]);
                        acc[jj][b] = fma2(Hn.y, w2[jj][1], acc[jj][b]);
                        acc[jj][b] = fma2(Ho.x, v2[jj][0], acc[jj][b]);
                        acc[jj][b] = fma2(Ho.y, v2[jj][1], acc[jj][b]);
                    }
                }
            }

            float z[4][4];
#pragma unroll
            for (int jj = 0; jj < 4; jj++)
#pragma unroll
                for (int b = 0; b < 4; b++) z[jj][b] = hadd2(acc[jj][b]) + b2j[jj];
#pragma unroll
            for (int b = 0; b < 4; b++) {
                c2[b] = sigf(z[1][b]) * c2[b] + sigf(z[0][b]) * tanhfast(z[2][b]);
                h2s[((nxt << 5) + b0g + b) * 64 + u] = sigf(z[3][b]) * tanhfast(c2[b]);
            }
        }
        __syncthreads();

        cur = nxt;
    }

    // final h2 in parity 0
    // ---------- dense head 1: d = sigmoid(h2 @ Wd + bd) -> stash in h1s ----------
    {
        const float bdv = bd[u];
#pragma unroll
        for (int b = 0; b < 4; b++) {
            float a = bdv;
#pragma unroll 8
            for (int k = 0; k < HU; k++)
                a += h2s[(b0g + b) * 64 + k] * Wd[k * HU + u];
            h1s[(b0g + b) * 64 + u] = sigf(a);
        }
    }
    __syncthreads();
    // ---------- dense head 2: out = sigmoid(d @ Wo + bo), warp per 2 rows ----------
    {
        const int w  = tid >> 5;
        const int ln = tid & 31;
        const float bov = bo[0];
        const float wo0 = Wo[ln], wo1 = Wo[ln + 32];
#pragma unroll
        for (int r = 0; r < 2; r++) {
            int row = w * 2 + r;
            float p = h1s[row * 64 + ln] * wo0 + h1s[row * 64 + ln + 32] * wo1;
#pragma unroll
            for (int s = 16; s; s >>= 1)
                p += __shfl_xor_sync(0xffffffffu, p, s);
            if (ln == 0)
                out[bglob + row] = sigf(p + bov);
        }
    }
}

extern "C" void kernel_launch(void* const* d_in, const int* in_sizes, int n_in,
                              void* d_out, int out_size)
{
    const float* x  = (const float*)d_in[0];
    const float* W1 = (const float*)d_in[1];
    const float* U1 = (const float*)d_in[2];
    const float* b1 = (const float*)d_in[3];
    const float* W2 = (const float*)d_in[4];
    const float* U2 = (const float*)d_in[5];
    const float* b2 = (const float*)d_in[6];
    const float* Wd = (const float*)d_in[7];
    const float* bd = (const float*)d_in[8];
    const float* Wo = (const float*)d_in[9];
    const float* bo = (const float*)d_in[10];
    float* out = (float*)d_out;

    // K1: xz prepass -> XZ[t][j][b]
    const size_t k1_smem = (8192 + K1_BT * 32) * sizeof(float);   // 48 KB
    cudaFuncSetAttribute(k1_xz, cudaFuncAttributeMaxDynamicSharedMemorySize, (int)k1_smem);
    k1_xz<<<K1_GRID, K1_NTH, k1_smem>>>(x, W1, b1);

    // K2: fused recurrence
    const size_t k2_smem = (size_t)K2_SMF * sizeof(float);        // 229376 B
    cudaFuncSetAttribute(k2_main, cudaFuncAttributeMaxDynamicSharedMemorySize, (int)k2_smem);
    k2_main<<<BATCH / BB, K2_NTH, k2_smem>>>(U1, W2, U2, b2, Wd, bd, Wo, bo, out);
}

// round 9
// speedup vs baseline: 1.8049x; 1.8049x over previous
#include <cuda_runtime.h>

#define HU      64
#define G4      256
#define T_STEPS 256
#define BATCH   4096
#define BB      32          // batch rows per K2 block
#define K2_NTH  256
#define K1_BT   128         // batch rows per K1 tile
#define K1_NTH  256
#define K1_TT   4           // timesteps per K1 block

typedef unsigned long long u64;

// 1 GB scratch: xz = x@W1 + b1, layout [t][j][b]
__device__ float XZ[(size_t)T_STEPS * G4 * BATCH];

__device__ __forceinline__ u64 fma2(u64 a, u64 b, u64 c) {
    u64 d;
    asm("fma.rn.f32x2 %0, %1, %2, %3;" : "=l"(d) : "l"(a), "l"(b), "l"(c));
    return d;
}
__device__ __forceinline__ float hadd2(u64 v) {
    float l, h;
    asm("mov.b64 {%0, %1}, %2;" : "=f"(l), "=f"(h) : "l"(v));
    return l + h;
}
__device__ __forceinline__ float fexp(float x) {
    float y;
    asm("ex2.approx.f32 %0, %1;" : "=f"(y) : "f"(x * 1.4426950408889634f));
    return y;
}
__device__ __forceinline__ float frcp(float x) {
    float y;
    asm("rcp.approx.f32 %0, %1;" : "=f"(y) : "f"(x));
    return y;
}
__device__ __forceinline__ float sigf(float x) { return frcp(1.0f + fexp(-x)); }
__device__ __forceinline__ float tanhfast(float x) {
    return fmaf(2.0f, frcp(1.0f + fexp(-2.0f * x)), -1.0f);
}

// ===================== K1: xz prepass, writes [t][j][b] =====================
// grid (32 btiles, 64 t-quads). Each block: W1 transpose once, 4 timesteps.
// x rows: [b][t][f] -> 4t*32f = 128 contiguous floats per row.
__global__ void __launch_bounds__(K1_NTH)
k1_xz(const float* __restrict__ x, const float* __restrict__ W1,
      const float* __restrict__ b1)
{
    extern __shared__ __align__(16) float sm1[];
    float* W1p = sm1;               // 8192 floats (k4-packed transpose)
    float* xs  = sm1 + 8192;        // 128 rows * 128 floats (4t x 32f)

    const int tid = threadIdx.x;
    const int b0  = blockIdx.x * K1_BT;
    const int t0  = blockIdx.y * K1_TT;

    for (int i = tid; i < 32 * G4; i += K1_NTH) {
        int f = i >> 8, j = i & 255;
        W1p[((f >> 2) << 10) + (j << 2) + (f & 3)] = W1[i];
    }
    // load 128 rows x 128 floats (each row = 4 consecutive t)
    for (int i = tid; i < K1_BT * 32; i += K1_NTH) {   // 4096 float4
        int row = i >> 5, q = i & 31;
        ((float4*)xs)[(row << 5) + q] =
            *(const float4*)(x + ((size_t)(b0 + row) * T_STEPS + t0) * 32 + q * 4);
    }
    __syncthreads();

    const int u  = tid & 63;
    const int bg = tid >> 6;
    float bj[4];
#pragma unroll
    for (int jj = 0; jj < 4; jj++) bj[jj] = b1[u + 64 * jj];

    for (int tt = 0; tt < K1_TT; tt++) {
        const int t = t0 + tt;
        for (int rep = 0; rep < 4; rep++) {
            const int rb = bg * 32 + rep * 8;
            u64 acc[4][8];
#pragma unroll
            for (int jj = 0; jj < 4; jj++)
#pragma unroll
                for (int b = 0; b < 8; b++) acc[jj][b] = 0ULL;

#pragma unroll
            for (int f4 = 0; f4 < 8; f4++) {
                u64 w[4][2];
#pragma unroll
                for (int jj = 0; jj < 4; jj++) {
                    ulonglong2 W = *(const ulonglong2*)&W1p[(f4 << 10) + ((u + 64 * jj) << 2)];
                    w[jj][0] = W.x; w[jj][1] = W.y;
                }
#pragma unroll
                for (int b = 0; b < 8; b++) {
                    ulonglong2 X = *(const ulonglong2*)&xs[((rb + b) << 7) + (tt << 5) + (f4 << 2)];
#pragma unroll
                    for (int jj = 0; jj < 4; jj++) {
                        acc[jj][b] = fma2(X.x, w[jj][0], acc[jj][b]);
                        acc[jj][b] = fma2(X.y, w[jj][1], acc[jj][b]);
                    }
                }
            }
#pragma unroll
            for (int jj = 0; jj < 4; jj++) {
                float z[8];
#pragma unroll
                for (int b = 0; b < 8; b++) z[b] = hadd2(acc[jj][b]) + bj[jj];
                float4* dst = (float4*)&XZ[((size_t)t * G4 + u + 64 * jj) * BATCH + b0 + rb];
                dst[0] = make_float4(z[0], z[1], z[2], z[3]);
                dst[1] = make_float4(z[4], z[5], z[6], z[7]);
            }
        }
    }
}

// ===================== K2: fused 2-layer recurrence + dense heads =====================
// 256 threads: u = tid&63 (unit, all 4 gates), bg = tid>>6 (8-row group). jt=4 x bt=8.
// ONE barrier per timestep (post-phase1); post-phase2 barrier proven removable:
//   phase1(t+1) writes h1s[parity cur_t] whose only readers finished before the
//   post-phase1 barrier of step t; all p2->p2 hazards fence at post-phase1(t+1).
#define K2_SMF 57344

__global__ void __launch_bounds__(K2_NTH, 1)
k2_main(const float* __restrict__ U1, const float* __restrict__ W2,
        const float* __restrict__ U2, const float* __restrict__ b2,
        const float* __restrict__ Wd, const float* __restrict__ bd,
        const float* __restrict__ Wo, const float* __restrict__ bo,
        float* __restrict__ out)
{
    extern __shared__ __align__(16) float sm[];
    float* U1p = sm;
    float* W2p = sm + 16384;
    float* U2p = sm + 32768;
    float* h1s = sm + 49152;
    float* h2s = sm + 53248;

    const int tid = threadIdx.x;

    for (int i = tid; i < HU * G4; i += K2_NTH) {
        int k = i >> 8, j = i & 255;
        int d = ((k >> 2) << 10) + (j << 2) + (k & 3);
        float a = U1[i], b = W2[i], c = U2[i];
        U1p[d] = a; W2p[d] = b; U2p[d] = c;
    }
    for (int i = tid; i < 4096; i += K2_NTH) { h1s[i] = 0.0f; h2s[i] = 0.0f; }

    const int u   = tid & 63;
    const int bg  = tid >> 6;
    const int b0g = bg * 8;
    const int bglob = blockIdx.x * BB;

    float b2j[4];
#pragma unroll
    for (int jj = 0; jj < 4; jj++) b2j[jj] = b2[u + 64 * jj];

    float c1[8], c2[8];
#pragma unroll
    for (int b = 0; b < 8; b++) { c1[b] = 0.0f; c2[b] = 0.0f; }

    // preload xz for t=0
    float4 xa[4], xb[4];
#pragma unroll
    for (int jj = 0; jj < 4; jj++) {
        const float* p = &XZ[((size_t)(u + 64 * jj)) * BATCH + bglob + b0g];
        xa[jj] = *(const float4*)p;
        xb[jj] = *(const float4*)(p + 4);
    }

    __syncthreads();

    int cur = 0;
    for (int t = 0; t < T_STEPS; t++) {
        const int nxt = cur ^ 1;

        // ---------- phase 1: z1 = xz + h1(t-1) @ U1 ; update c1, h1 ----------
        {
            u64 acc[4][8];
#pragma unroll
            for (int jj = 0; jj < 4; jj++)
#pragma unroll
                for (int b = 0; b < 8; b++) acc[jj][b] = 0ULL;

#pragma unroll 4
            for (int k4 = 0; k4 < 16; k4++) {
                u64 w[4][2];
#pragma unroll
                for (int jj = 0; jj < 4; jj++) {
                    ulonglong2 W = *(const ulonglong2*)&U1p[(k4 << 10) + ((u + 64 * jj) << 2)];
                    w[jj][0] = W.x; w[jj][1] = W.y;
                }
#pragma unroll
                for (int b = 0; b < 8; b++) {
                    ulonglong2 H = *(const ulonglong2*)&h1s[((cur << 5) + b0g + b) * 64 + (k4 << 2)];
#pragma unroll
                    for (int jj = 0; jj < 4; jj++) {
                        acc[jj][b] = fma2(H.x, w[jj][0], acc[jj][b]);
                        acc[jj][b] = fma2(H.y, w[jj][1], acc[jj][b]);
                    }
                }
            }

            float z[4][8];
#pragma unroll
            for (int jj = 0; jj < 4; jj++) {
#pragma unroll
                for (int b = 0; b < 8; b++) z[jj][b] = hadd2(acc[jj][b]);
                z[jj][0] += xa[jj].x; z[jj][1] += xa[jj].y;
                z[jj][2] += xa[jj].z; z[jj][3] += xa[jj].w;
                z[jj][4] += xb[jj].x; z[jj][5] += xb[jj].y;
                z[jj][6] += xb[jj].z; z[jj][7] += xb[jj].w;
            }
#pragma unroll
            for (int b = 0; b < 8; b++) {
                c1[b] = sigf(z[1][b]) * c1[b] + sigf(z[0][b]) * tanhfast(z[2][b]);
                h1s[((nxt << 5) + b0g + b) * 64 + u] = sigf(z[3][b]) * tanhfast(c1[b]);
            }
        }
        __syncthreads();

        // ---------- phase 2: z2 = h1(t)@W2 + h2(t-1)@U2 + b2 ; update c2, h2 ----------
        // (no trailing barrier — see proof above)
        {
            // prefetch next step's xz into registers (consumed after next barrier)
            const int tn = (t + 1) & 255;
#pragma unroll
            for (int jj = 0; jj < 4; jj++) {
                const float* p = &XZ[((size_t)tn * G4 + u + 64 * jj) * BATCH + bglob + b0g];
                xa[jj] = *(const float4*)p;
                xb[jj] = *(const float4*)(p + 4);
            }

            u64 acc[4][8];
#pragma unroll
            for (int jj = 0; jj < 4; jj++)
#pragma unroll
                for (int b = 0; b < 8; b++) acc[jj][b] = 0ULL;

#pragma unroll 2
            for (int k4 = 0; k4 < 16; k4++) {
                u64 w2[4][2], v2[4][2];
#pragma unroll
                for (int jj = 0; jj < 4; jj++) {
                    ulonglong2 W = *(const ulonglong2*)&W2p[(k4 << 10) + ((u + 64 * jj) << 2)];
                    w2[jj][0] = W.x; w2[jj][1] = W.y;
                    ulonglong2 V = *(const ulonglong2*)&U2p[(k4 << 10) + ((u + 64 * jj) << 2)];
                    v2[jj][0] = V.x; v2[jj][1] = V.y;
                }
#pragma unroll
                for (int b = 0; b < 8; b++) {
                    ulonglong2 Hn = *(const ulonglong2*)&h1s[((nxt << 5) + b0g + b) * 64 + (k4 << 2)];
                    ulonglong2 Ho = *(const ulonglong2*)&h2s[((cur << 5) + b0g + b) * 64 + (k4 << 2)];
#pragma unroll
                    for (int jj = 0; jj < 4; jj++) {
                        acc[jj][b] = fma2(Hn.x, w2[jj][0], acc[jj][b]);
                        acc[jj][b] = fma2(Hn.y, w2[jj][1], acc[jj][b]);
                        acc[jj][b] = fma2(Ho.x, v2[jj][0], acc[jj][b]);
                        acc[jj][b] = fma2(Ho.y, v2[jj][1], acc[jj][b]);
                    }
                }
            }

            float z[4][8];
#pragma unroll
            for (int jj = 0; jj < 4; jj++)
#pragma unroll
                for (int b = 0; b < 8; b++) z[jj][b] = hadd2(acc[jj][b]) + b2j[jj];
#pragma unroll
            for (int b = 0; b < 8; b++) {
                c2[b] = sigf(z[1][b]) * c2[b] + sigf(z[0][b]) * tanhfast(z[2][b]);
                h2s[((nxt << 5) + b0g + b) * 64 + u] = sigf(z[3][b]) * tanhfast(c2[b]);
            }
        }

        cur = nxt;
    }
    __syncthreads();   // fence last phase-2 h2 writes before dense heads

    // final h2 in parity 0
    // ---------- dense head 1: d = sigmoid(h2 @ Wd + bd) -> stash in h1s ----------
    {
        const float bdv = bd[u];
#pragma unroll
        for (int b = 0; b < 8; b++) {
            float a = bdv;
#pragma unroll 8
            for (int k = 0; k < HU; k++)
                a += h2s[(b0g + b) * 64 + k] * Wd[k * HU + u];
            h1s[(b0g + b) * 64 + u] = sigf(a);
        }
    }
    __syncthreads();
    // ---------- dense head 2: out = sigmoid(d @ Wo + bo), warp per 4 rows ----------
    {
        const int w  = tid >> 5;
        const int ln = tid & 31;
        const float bov = bo[0];
        const float wo0 = Wo[ln], wo1 = Wo[ln + 32];
#pragma unroll
        for (int r = 0; r < 4; r++) {
            int row = w * 4 + r;
            float p = h1s[row * 64 + ln] * wo0 + h1s[row * 64 + ln + 32] * wo1;
#pragma unroll
            for (int s = 16; s; s >>= 1)
                p += __shfl_xor_sync(0xffffffffu, p, s);
            if (ln == 0)
                out[bglob + row] = sigf(p + bov);
        }
    }
}

extern "C" void kernel_launch(void* const* d_in, const int* in_sizes, int n_in,
                              void* d_out, int out_size)
{
    const float* x  = (const float*)d_in[0];
    const float* W1 = (const float*)d_in[1];
    const float* U1 = (const float*)d_in[2];
    const float* b1 = (const float*)d_in[3];
    const float* W2 = (const float*)d_in[4];
    const float* U2 = (const float*)d_in[5];
    const float* b2 = (const float*)d_in[6];
    const float* Wd = (const float*)d_in[7];
    const float* bd = (const float*)d_in[8];
    const float* Wo = (const float*)d_in[9];
    const float* bo = (const float*)d_in[10];
    float* out = (float*)d_out;

    // K1: xz prepass -> XZ[t][j][b]
    const size_t k1_smem = (8192 + K1_BT * 32 * K1_TT) * sizeof(float);   // 96 KB
    cudaFuncSetAttribute(k1_xz, cudaFuncAttributeMaxDynamicSharedMemorySize, (int)k1_smem);
    dim3 g1(BATCH / K1_BT, T_STEPS / K1_TT);
    k1_xz<<<g1, K1_NTH, k1_smem>>>(x, W1, b1);

    // K2: fused recurrence
    const size_t k2_smem = (size_t)K2_SMF * sizeof(float);        // 229376 B
    cudaFuncSetAttribute(k2_main, cudaFuncAttributeMaxDynamicSharedMemorySize, (int)k2_smem);
    k2_main<<<BATCH / BB, K2_NTH, k2_smem>>>(U1, W2, U2, b2, Wd, bd, Wo, bo, out);
}